// round 12
// baseline (speedup 1.0000x reference)
#include <cuda_runtime.h>

// ---------------------------------------------------------------------------
// TransformDomainInterpolator — GB300 sm_103a
//
// Identity (verified against the reference algebra):
//   freq_interp[2m]   = est[m]                                    (exact)
//   freq_interp[2m+1] = (1/2048) * IDFT2048( DFT2048(est)[k] * phi[k] )[m]
//   phi[k] = +e^{i pi k/2048} (k<1024),  -e^{i pi k/2048} (k>=1024)
// Time interp: c(t) = clamp((t-2)/9, 0, 1) between pilot symbols 2 and 11.
//
// OUTPUT LAYOUT (round-10 finding, rel_err == sqrt(2) fingerprint): planar —
//   out[0      .. N)  = real part of [B, 14, 4096]
//   out[N      .. 2N) = imag part,          N = B*14*4096
//
// One block per batch element; Stockham radix-2 2048-pt fwd+inv FFT in 40KB
// static shared memory; twiddles via sincospif.
// ---------------------------------------------------------------------------

#define NTH  512
#define NFFT 2048
#define HALF 1024
#define NSYM 14

__device__ __forceinline__ float gload(const float* p, long long i, long long lim) {
    return (i < lim) ? __ldg(p + i) : 0.0f;
}

__global__ __launch_bounds__(NTH)
void fused_interp_kernel(const float* __restrict__ re,
                         const float* __restrict__ im,
                         float* __restrict__ out,
                         long long n_re, long long n_im, long long n_out,
                         long long plane)                 // N = batch*14*4096
{
    __shared__ float2 sA[NFFT];
    __shared__ float2 sB[NFFT];
    __shared__ float2 stw[HALF];

    const int b   = blockIdx.x;
    const int tid = threadIdx.x;

    // twiddles: stw[q] = exp(-2*pi*i*q/2048), q in [0,1024)
    for (int i = tid; i < HALF; i += NTH) {
        float sn, cs;
        sincospif(-(float)i * (1.0f / 1024.0f), &sn, &cs);
        stw[i] = make_float2(cs, sn);
    }

    const long long base = (long long)b * (2 * NFFT);

    float2 O[2][4];   // odd-sample results: O[sym][k] = odd[tid + k*512]

    for (int sym = 0; sym < 2; sym++) {
        const long long sb = base + sym * NFFT;
        float2 e0 = make_float2(gload(re, sb + tid,        n_re), gload(im, sb + tid,        n_im));
        float2 e1 = make_float2(gload(re, sb + tid + 512,  n_re), gload(im, sb + tid + 512,  n_im));
        float2 e2 = make_float2(gload(re, sb + tid + 1024, n_re), gload(im, sb + tid + 1024, n_im));
        float2 e3 = make_float2(gload(re, sb + tid + 1536, n_re), gload(im, sb + tid + 1536, n_im));

        __syncthreads();   // sym0: stw ready; sym1: sA reads of prev iter done

        // forward stage 0 (Ns=1, w=1): registers -> sA
        sA[2 * tid]             = make_float2(e0.x + e2.x, e0.y + e2.y);
        sA[2 * tid + 1]         = make_float2(e0.x - e2.x, e0.y - e2.y);
        sA[2 * (tid + 512)]     = make_float2(e1.x + e3.x, e1.y + e3.y);
        sA[2 * (tid + 512) + 1] = make_float2(e1.x - e3.x, e1.y - e3.y);
        __syncthreads();

        // forward stages 1..10: sA <-> sB, spectrum ends in sA
        {
            const float2* src = sA;
            int Ns = 2;
            for (int st = 1; st < 11; st++) {
                float2* dst = (st & 1) ? sB : sA;
                const int twmul = HALF / Ns;
                for (int j = tid; j < HALF; j += NTH) {
                    float2 a  = src[j];
                    float2 bb = src[j + HALF];
                    int r = j & (Ns - 1);
                    float2 w = stw[r * twmul];
                    float2 t = make_float2(bb.x * w.x - bb.y * w.y,
                                           bb.x * w.y + bb.y * w.x);
                    int d = ((j - r) << 1) + r;
                    dst[d]      = make_float2(a.x + t.x, a.y + t.y);
                    dst[d + Ns] = make_float2(a.x - t.x, a.y - t.y);
                }
                __syncthreads();
                src = dst;
                Ns <<= 1;
            }
        }

        // inverse stage 0 (Ns=1, w=1) with phi[k]/2048 fused: sA -> sB
        for (int j = tid; j < HALF; j += NTH) {
            float2 fa = sA[j];
            float2 fb = sA[j + HALF];
            float sn, cs;
            sincospif((float)j * (1.0f / 2048.0f), &sn, &cs);
            float2 pa = make_float2(cs * (1.0f / 2048.0f), sn * (1.0f / 2048.0f));
            sincospif((float)(j + HALF) * (1.0f / 2048.0f), &sn, &cs);
            float2 pb = make_float2(-cs * (1.0f / 2048.0f), -sn * (1.0f / 2048.0f));
            float2 a = make_float2(fa.x * pa.x - fa.y * pa.y,
                                   fa.x * pa.y + fa.y * pa.x);
            float2 t = make_float2(fb.x * pb.x - fb.y * pb.y,
                                   fb.x * pb.y + fb.y * pb.x);
            sB[2 * j]     = make_float2(a.x + t.x, a.y + t.y);
            sB[2 * j + 1] = make_float2(a.x - t.x, a.y - t.y);
        }
        __syncthreads();

        // inverse stages 1..9 (conjugate twiddles): sB <-> sA, ends in sA
        {
            const float2* src = sB;
            int Ns = 2;
            for (int st = 1; st < 10; st++) {
                float2* dst = (st & 1) ? sA : sB;
                const int twmul = HALF / Ns;
                for (int j = tid; j < HALF; j += NTH) {
                    float2 a  = src[j];
                    float2 bb = src[j + HALF];
                    int r = j & (Ns - 1);
                    float2 w = stw[r * twmul];
                    float2 t = make_float2(bb.x * w.x + bb.y * w.y,
                                           bb.y * w.x - bb.x * w.y);
                    int d = ((j - r) << 1) + r;
                    dst[d]      = make_float2(a.x + t.x, a.y + t.y);
                    dst[d + Ns] = make_float2(a.x - t.x, a.y - t.y);
                }
                __syncthreads();
                src = dst;
                Ns <<= 1;
            }
        }

        // inverse stage 10 (Ns=1024, r=j, d=j): sA -> registers
        {
            float2 a  = sA[tid];
            float2 bb = sA[tid + HALF];
            float2 w  = stw[tid];
            float2 t  = make_float2(bb.x * w.x + bb.y * w.y,
                                    bb.y * w.x - bb.x * w.y);
            O[sym][0] = make_float2(a.x + t.x, a.y + t.y);
            O[sym][2] = make_float2(a.x - t.x, a.y - t.y);

            a  = sA[tid + 512];
            bb = sA[tid + 512 + HALF];
            w  = stw[tid + 512];
            t  = make_float2(bb.x * w.x + bb.y * w.y,
                             bb.y * w.x - bb.x * w.y);
            O[sym][1] = make_float2(a.x + t.x, a.y + t.y);
            O[sym][3] = make_float2(a.x - t.x, a.y - t.y);
        }
        // next iteration's first __syncthreads() protects sA before reuse
    }

    // even samples = raw pilots (guarded reloads; L1/L2 hits)
    float2 E0[4], E1[4];
#pragma unroll
    for (int k = 0; k < 4; k++) {
        long long m = tid + k * 512;
        E0[k] = make_float2(gload(re, base + m,        n_re), gload(im, base + m,        n_im));
        E1[k] = make_float2(gload(re, base + NFFT + m, n_re), gload(im, base + NFFT + m, n_im));
    }

    // planar output: real plane at [0, plane), imag plane at [plane, 2*plane).
    // element index c = b*14*4096 + t*4096 + n; even n=2m, odd n=2m+1 adjacent.
    const long long cb = (long long)b * (NSYM * 2 * NFFT);
#pragma unroll
    for (int t = 0; t < NSYM; t++) {
        float c = (t <= 2) ? 0.0f
                : (t >= 11) ? 1.0f
                : (float)(t - 2) * (1.0f / 9.0f);
        const long long ct = cb + (long long)t * (2 * NFFT);
#pragma unroll
        for (int k = 0; k < 4; k++) {
            int m = tid + k * 512;
            float2 ev, od;
            ev.x = E0[k].x + (E1[k].x - E0[k].x) * c;
            ev.y = E0[k].y + (E1[k].y - E0[k].y) * c;
            od.x = O[0][k].x + (O[1][k].x - O[0][k].x) * c;
            od.y = O[0][k].y + (O[1][k].y - O[0][k].y) * c;
            long long fr = ct + 2 * m;          // float idx in real plane
            long long fi = plane + ct + 2 * m;  // float idx in imag plane
            if (fr + 1 < n_out)
                *reinterpret_cast<float2*>(out + fr) = make_float2(ev.x, od.x);
            if (fi + 1 < n_out)
                *reinterpret_cast<float2*>(out + fi) = make_float2(ev.y, od.y);
        }
    }
}

extern "C" void kernel_launch(void* const* d_in, const int* in_sizes, int n_in,
                              void* d_out, int out_size) {
    if (n_in < 2 || !d_out) return;
    const float* re = (const float*)d_in[0];
    const float* im = (const float*)d_in[1];

    long long n_re = in_sizes[0];
    long long n_im = in_sizes[1];
    int batch = (int)(n_re / (2 * NFFT));
    if (batch <= 0) return;

    long long plane = (long long)batch * NSYM * 2 * NFFT;   // B*14*4096

    fused_interp_kernel<<<batch, NTH>>>(re, im, (float*)d_out,
                                        n_re, n_im, (long long)out_size, plane);
}

// round 17
// speedup vs baseline: 1.7707x; 1.7707x over previous
#include <cuda_runtime.h>

// ---------------------------------------------------------------------------
// TransformDomainInterpolator — GB300 sm_103a — radix-4 Stockham core inside
// the round-12 (passing) shell: guarded loads/stores, launch_bounds(512).
//
// Identity (verified, passing at rel_err 2.2e-7 in round 12):
//   freq_interp[2m]   = est[m]                                    (exact)
//   freq_interp[2m+1] = (1/2048) * IDFT2048( DFT2048(est)[k] * phi[k] )[m]
//   phi[k] = +e^{i pi k/2048} (k<1024),  -e^{i pi k/2048} (k>=1024)
// Time interp: c(t) = clamp((t-2)/9, 0, 1) between pilot symbols 2 and 11.
// Output layout: planar float32 — real plane [0,N), imag plane [N,2N),
//   N = B*14*4096.
//
// 2048 = 2 * 4^5: one radix-2 stage + five radix-4 stages per transform.
// 512 threads -> exactly one radix-4 butterfly per thread per stage.
// ---------------------------------------------------------------------------

#define NTH  512
#define NFFT 2048
#define NSYM 14

__device__ __forceinline__ float gload(const float* p, long long i, long long lim) {
    return (i < lim) ? __ldg(p + i) : 0.0f;
}

__device__ __forceinline__ float2 cmul(float2 a, float2 b) {
    return make_float2(fmaf(a.x, b.x, -a.y * b.y),
                       fmaf(a.x, b.y,  a.y * b.x));
}

// One Stockham radix-4 stage, 512 butterflies, one per thread.
// src/dst: 2048-entry float2 smem buffers. stw4[q] = exp(-2*pi*i*q/2048), q<512.
template <int Ns, bool INV>
__device__ __forceinline__ void r4_stage(const float2* __restrict__ src,
                                         float2* __restrict__ dst,
                                         const float2* __restrict__ stw4,
                                         int tid)
{
    const int r = tid & (Ns - 1);
    const int d = ((tid - r) << 2) + r;
    float2 x0 = src[tid];
    float2 x1 = src[tid + 512];
    float2 x2 = src[tid + 1024];
    float2 x3 = src[tid + 1536];
    float2 w1 = stw4[r * (512 / Ns)];      // W_{4Ns}^r
    if (INV) w1.y = -w1.y;
    float2 w2 = cmul(w1, w1);
    float2 w3 = cmul(w2, w1);
    float2 t1 = cmul(x1, w1);
    float2 t2 = cmul(x2, w2);
    float2 t3 = cmul(x3, w3);
    float2 u0 = make_float2(x0.x + t2.x, x0.y + t2.y);
    float2 u1 = make_float2(x0.x - t2.x, x0.y - t2.y);
    float2 u2 = make_float2(t1.x + t3.x, t1.y + t3.y);
    float2 u3 = INV ? make_float2(-(t1.y - t3.y),  (t1.x - t3.x))    //  +i*(t1-t3)
                    : make_float2( (t1.y - t3.y), -(t1.x - t3.x));   //  -i*(t1-t3)
    dst[d]          = make_float2(u0.x + u2.x, u0.y + u2.y);
    dst[d + Ns]     = make_float2(u1.x + u3.x, u1.y + u3.y);
    dst[d + 2 * Ns] = make_float2(u0.x - u2.x, u0.y - u2.y);
    dst[d + 3 * Ns] = make_float2(u1.x - u3.x, u1.y - u3.y);
}

__global__ __launch_bounds__(NTH)
void fused_interp_kernel(const float* __restrict__ re,
                         const float* __restrict__ im,
                         float* __restrict__ out,
                         long long n_re, long long n_im, long long n_out,
                         long long plane)                 // N = batch*14*4096
{
    __shared__ float2 sA[NFFT];
    __shared__ float2 sB[NFFT];
    __shared__ float2 stw4[512];

    const int b   = blockIdx.x;
    const int tid = threadIdx.x;

    // stw4[q] = exp(-2*pi*i*q/2048), q in [0,512)
    {
        float sn, cs;
        sincospif(-(float)tid * (1.0f / 1024.0f), &sn, &cs);
        stw4[tid] = make_float2(cs, sn);
    }

    const long long base = (long long)b * (2 * NFFT);

    float2 O[2][4];   // odd-sample results: O[sym][k] = odd[tid + k*512]

    for (int sym = 0; sym < 2; sym++) {
        const long long sb = base + sym * NFFT;
        float2 e0 = make_float2(gload(re, sb + tid,        n_re), gload(im, sb + tid,        n_im));
        float2 e1 = make_float2(gload(re, sb + tid + 512,  n_re), gload(im, sb + tid + 512,  n_im));
        float2 e2 = make_float2(gload(re, sb + tid + 1024, n_re), gload(im, sb + tid + 1024, n_im));
        float2 e3 = make_float2(gload(re, sb + tid + 1536, n_re), gload(im, sb + tid + 1536, n_im));

        __syncthreads();   // sym0: stw4 ready; sym1: prev iter's sA reads done

        // forward radix-2 stage (Ns=1, w=1): registers -> sA
        sA[2 * tid]             = make_float2(e0.x + e2.x, e0.y + e2.y);
        sA[2 * tid + 1]         = make_float2(e0.x - e2.x, e0.y - e2.y);
        sA[2 * (tid + 512)]     = make_float2(e1.x + e3.x, e1.y + e3.y);
        sA[2 * (tid + 512) + 1] = make_float2(e1.x - e3.x, e1.y - e3.y);
        __syncthreads();

        // forward radix-4 stages: Ns = 2,8,32,128,512 -> spectrum in sB
        r4_stage<2,   false>(sA, sB, stw4, tid); __syncthreads();
        r4_stage<8,   false>(sB, sA, stw4, tid); __syncthreads();
        r4_stage<32,  false>(sA, sB, stw4, tid); __syncthreads();
        r4_stage<128, false>(sB, sA, stw4, tid); __syncthreads();
        r4_stage<512, false>(sA, sB, stw4, tid); __syncthreads();

        // inverse radix-2 stage (Ns=1, w=1) with phi[k]/2048 fused: sB -> sA
#pragma unroll
        for (int u = 0; u < 2; u++) {
            int j = tid + u * 512;
            float2 fa = sB[j];
            float2 fb = sB[j + 1024];
            float sn, cs;
            sincospif((float)j * (1.0f / 2048.0f), &sn, &cs);
            float2 pa = make_float2(cs * (1.0f / 2048.0f), sn * (1.0f / 2048.0f));
            sincospif((float)(j + 1024) * (1.0f / 2048.0f), &sn, &cs);
            float2 pb = make_float2(-cs * (1.0f / 2048.0f), -sn * (1.0f / 2048.0f));
            float2 a = cmul(fa, pa);
            float2 t = cmul(fb, pb);
            sA[2 * j]     = make_float2(a.x + t.x, a.y + t.y);
            sA[2 * j + 1] = make_float2(a.x - t.x, a.y - t.y);
        }
        __syncthreads();

        // inverse radix-4 stages: Ns = 2,8,32,128 in smem
        r4_stage<2,   true>(sA, sB, stw4, tid); __syncthreads();
        r4_stage<8,   true>(sB, sA, stw4, tid); __syncthreads();
        r4_stage<32,  true>(sA, sB, stw4, tid); __syncthreads();
        r4_stage<128, true>(sB, sA, stw4, tid); __syncthreads();

        // final inverse radix-4 stage (Ns=512): r=tid, d=tid -> registers.
        // outputs land at tid + q*512 == this thread's O[sym][q] slice.
        {
            float2 x0 = sA[tid];
            float2 x1 = sA[tid + 512];
            float2 x2 = sA[tid + 1024];
            float2 x3 = sA[tid + 1536];
            float2 w1 = stw4[tid]; w1.y = -w1.y;
            float2 w2 = cmul(w1, w1);
            float2 w3 = cmul(w2, w1);
            float2 t1 = cmul(x1, w1);
            float2 t2 = cmul(x2, w2);
            float2 t3 = cmul(x3, w3);
            float2 u0 = make_float2(x0.x + t2.x, x0.y + t2.y);
            float2 u1 = make_float2(x0.x - t2.x, x0.y - t2.y);
            float2 u2 = make_float2(t1.x + t3.x, t1.y + t3.y);
            float2 u3 = make_float2(-(t1.y - t3.y), (t1.x - t3.x));
            O[sym][0] = make_float2(u0.x + u2.x, u0.y + u2.y);
            O[sym][1] = make_float2(u1.x + u3.x, u1.y + u3.y);
            O[sym][2] = make_float2(u0.x - u2.x, u0.y - u2.y);
            O[sym][3] = make_float2(u1.x - u3.x, u1.y - u3.y);
        }
        // next iteration's first __syncthreads() protects sA before reuse
    }

    // even samples = raw pilots (guarded reloads; L1/L2 hits)
    float2 E0[4], E1[4];
#pragma unroll
    for (int k = 0; k < 4; k++) {
        long long m = tid + k * 512;
        E0[k] = make_float2(gload(re, base + m,        n_re), gload(im, base + m,        n_im));
        E1[k] = make_float2(gload(re, base + NFFT + m, n_re), gload(im, base + NFFT + m, n_im));
    }

    // planar output: real plane [0,plane), imag plane [plane,2*plane).
    // element index c = b*14*4096 + t*4096 + n; even n=2m, odd n=2m+1 adjacent.
    const long long cb = (long long)b * (NSYM * 2 * NFFT);
#pragma unroll
    for (int t = 0; t < NSYM; t++) {
        float c = (t <= 2) ? 0.0f
                : (t >= 11) ? 1.0f
                : (float)(t - 2) * (1.0f / 9.0f);
        const long long ct = cb + (long long)t * (2 * NFFT);
#pragma unroll
        for (int k = 0; k < 4; k++) {
            int m = tid + k * 512;
            float evx = fmaf(E1[k].x - E0[k].x, c, E0[k].x);
            float evy = fmaf(E1[k].y - E0[k].y, c, E0[k].y);
            float odx = fmaf(O[1][k].x - O[0][k].x, c, O[0][k].x);
            float ody = fmaf(O[1][k].y - O[0][k].y, c, O[0][k].y);
            long long fr = ct + 2 * m;          // float idx in real plane
            long long fi = plane + ct + 2 * m;  // float idx in imag plane
            if (fr + 1 < n_out)
                *reinterpret_cast<float2*>(out + fr) = make_float2(evx, odx);
            if (fi + 1 < n_out)
                *reinterpret_cast<float2*>(out + fi) = make_float2(evy, ody);
        }
    }
}

extern "C" void kernel_launch(void* const* d_in, const int* in_sizes, int n_in,
                              void* d_out, int out_size) {
    if (n_in < 2 || !d_out) return;
    const float* re = (const float*)d_in[0];
    const float* im = (const float*)d_in[1];

    long long n_re = in_sizes[0];
    long long n_im = in_sizes[1];
    int batch = (int)(n_re / (2 * NFFT));
    if (batch <= 0) return;

    long long plane = (long long)batch * NSYM * 2 * NFFT;   // B*14*4096

    fused_interp_kernel<<<batch, NTH>>>(re, im, (float*)d_out,
                                        n_re, n_im, (long long)out_size, plane);
}